// round 10
// baseline (speedup 1.0000x reference)
#include <cuda_runtime.h>
#include <stdint.h>

// out[b,d] = x[b,d] * |W[d,d]|, fused single kernel. FINAL (converged R4/R7 shape):
// - blockDim=256, D/4=256 float4 column groups => (i mod 256)==threadIdx.x
//   for every grid-stride iteration, so each thread's diag float4 is
//   loop-invariant and loaded once in the prologue (W diag is L2-resident).
// - __ldcs/__stcs: x/out have zero reuse, evict-first keeps L2 clean.
// - 32 regs, ~92% occupancy, 2368 blocks (2 waves).
// Measured at the HBM roofline for 1:1 R/W streams: 6.1-6.2 TB/s (~77% of
// 8 TB/s spec; remainder is bus-turnaround cost of read/write interleave).
__global__ void __launch_bounds__(256) diag_mul_kernel(
    const float4* __restrict__ x4,
    const float* __restrict__ W,
    float4* __restrict__ out4,
    long n4, int D) {
    // This thread's 4 diagonal elements: columns 4*tid .. 4*tid+3.
    int c = threadIdx.x * 4;
    float4 d;
    d.x = fabsf(__ldg(&W[(size_t)(c + 0) * (D + 1)]));
    d.y = fabsf(__ldg(&W[(size_t)(c + 1) * (D + 1)]));
    d.z = fabsf(__ldg(&W[(size_t)(c + 2) * (D + 1)]));
    d.w = fabsf(__ldg(&W[(size_t)(c + 3) * (D + 1)]));

    const long stride = (long)gridDim.x * blockDim.x;  // multiple of 256
    for (long i = (long)blockIdx.x * blockDim.x + threadIdx.x; i < n4; i += stride) {
        float4 v = __ldcs(&x4[i]);
        v.x *= d.x;
        v.y *= d.y;
        v.z *= d.z;
        v.w *= d.w;
        __stcs(&out4[i], v);
    }
}

extern "C" void kernel_launch(void* const* d_in, const int* in_sizes, int n_in,
                              void* d_out, int out_size) {
    const float* x = (const float*)d_in[0];
    const float* W = (const float*)d_in[1];
    float* out = (float*)d_out;

    const int D = 1024;
    const long n4 = (long)out_size / 4;  // 2^24 for 65536x1024

    int blocks = 148 * 16;  // 2368; 8 resident blocks/SM at 32 regs
    diag_mul_kernel<<<blocks, 256>>>(
        reinterpret_cast<const float4*>(x), W,
        reinterpret_cast<float4*>(out), n4, D);
}

// round 12
// speedup vs baseline: 1.0511x; 1.0511x over previous
#include <cuda_runtime.h>
#include <stdint.h>

// out[b,d] = x[b,d] * |W[d,d]|, fused single kernel. FINAL (converged shape):
// - blockDim=256, D/4=256 float4 column groups => (i mod 256)==threadIdx.x
//   for every grid-stride iteration, so each thread's diag float4 is
//   loop-invariant and loaded once in the prologue (W diag is L2-resident).
// - __ldcs/__stcs: x/out have zero reuse, evict-first keeps L2 clean.
// - 32 regs, ~92% occupancy, 2368 blocks (2 waves).
// At the HBM roofline for 1:1 R/W streams: 6.0-6.2 TB/s (~77% of 8 TB/s
// spec; the remainder is memory-controller read/write turnaround, not
// addressable from the SM). Run-to-run variance on identical SASS: +/-4us.
__global__ void __launch_bounds__(256) diag_mul_kernel(
    const float4* __restrict__ x4,
    const float* __restrict__ W,
    float4* __restrict__ out4,
    long n4, int D) {
    // This thread's 4 diagonal elements: columns 4*tid .. 4*tid+3.
    int c = threadIdx.x * 4;
    float4 d;
    d.x = fabsf(__ldg(&W[(size_t)(c + 0) * (D + 1)]));
    d.y = fabsf(__ldg(&W[(size_t)(c + 1) * (D + 1)]));
    d.z = fabsf(__ldg(&W[(size_t)(c + 2) * (D + 1)]));
    d.w = fabsf(__ldg(&W[(size_t)(c + 3) * (D + 1)]));

    const long stride = (long)gridDim.x * blockDim.x;  // multiple of 256
    for (long i = (long)blockIdx.x * blockDim.x + threadIdx.x; i < n4; i += stride) {
        float4 v = __ldcs(&x4[i]);
        v.x *= d.x;
        v.y *= d.y;
        v.z *= d.z;
        v.w *= d.w;
        __stcs(&out4[i], v);
    }
}

extern "C" void kernel_launch(void* const* d_in, const int* in_sizes, int n_in,
                              void* d_out, int out_size) {
    const float* x = (const float*)d_in[0];
    const float* W = (const float*)d_in[1];
    float* out = (float*)d_out;

    const int D = 1024;
    const long n4 = (long)out_size / 4;  // 2^24 for 65536x1024

    int blocks = 148 * 16;  // 2368; 8 resident blocks/SM at 32 regs
    diag_mul_kernel<<<blocks, 256>>>(
        reinterpret_cast<const float4*>(x), W,
        reinterpret_cast<float4*>(out), n4, D);
}